// round 17
// baseline (speedup 1.0000x reference)
#include <cuda_runtime.h>
#include <cuda_fp16.h>
#include <cstdint>

// ---------------------------------------------------------------------------
// NeRF fused MLP via mma.sync m16n8k16, pure f16 GEMM (fp32 accum),
// rel_err 1.84e-4 (R16).  TM=64/CTA, 256 thr (8 warps, 2x4), 2 CTAs/SM.
// NEW (R17): 64-K W chunks (stride 144 B) -> half the barriers/waits, 4
// unrolled k-steps of straight-line LDSM+MMA between syncs.
// W pre-converted once to a __device__ f16 blob in [chunk64][n][k] order;
// per-wn-group cp.async staging (named bars 1-4, 64 thr); ldmatrix frags;
// same-NW cross-layer prefetch; row-group epilogue barriers (5-6, 128 thr).
// ---------------------------------------------------------------------------

#define NT 256

// A: [64][280] halves (single plane), row stride 560 B (bank shift 12)
#define SA_B   560
#define A_HI   0
// W double buffer: 256 n-rows x 144 B (128 data + 16 pad)
#define W_BASE 35840
#define W_BUFB 36864            // byte stride between buffer 0 and 1
// hc f32 [64][132] overlaid on W region (dead during head)
#define HCOFF  35840
#define SHC_B  528
#define WCOL0  109568
#define WC1O   110592
#define SMEM_SZ 112128          // x2 CTAs = 224.3 KB <= 227 KB SM limit

// weight blob layout (halves), [chunk(64k)][n][64k] per layer:
//  L0   @ 0      : 1 chunk 256n x 32k (k>=30 zero)          = 8192
//  L1-7 @ 8192+(L-1)*65536 : 4 chunks x (256n x 64k)        = 65536 each
//  L8   @ 466944 : 4 chunks (cols 1..256 shifted)           = 65536
//  Wc0  @ 532480 : 4 chunks x (128n x 64k) + 1 x (128n x 16k), k>=268 zero
#define BLOB_N 567296
__device__ __half g_whi[BLOB_N];

struct Params {
    const float* x; const float* d;
    const float* W[9]; const float* b[9];
    const float* Wc0; const float* bc0;
    const float* Wc1; const float* bc1;
};

__device__ __forceinline__ void mma16816(float c[4], uint32_t a0, uint32_t a1,
                                         uint32_t a2, uint32_t a3,
                                         uint32_t b0, uint32_t b1) {
    asm("mma.sync.aligned.m16n8k16.row.col.f32.f16.f16.f32 "
        "{%0,%1,%2,%3}, {%4,%5,%6,%7}, {%8,%9}, {%0,%1,%2,%3};"
        : "+f"(c[0]), "+f"(c[1]), "+f"(c[2]), "+f"(c[3])
        : "r"(a0), "r"(a1), "r"(a2), "r"(a3), "r"(b0), "r"(b1));
}
__device__ __forceinline__ void ldsm4(uint32_t r[4], uint32_t addr) {
    asm volatile("ldmatrix.sync.aligned.m8n8.x4.shared.b16 {%0,%1,%2,%3}, [%4];"
                 : "=r"(r[0]), "=r"(r[1]), "=r"(r[2]), "=r"(r[3]) : "r"(addr));
}
__device__ __forceinline__ uint32_t pack2(__half a, __half b) {
    return (uint32_t)__half_as_ushort(a) | ((uint32_t)__half_as_ushort(b) << 16);
}
__device__ __forceinline__ uint32_t packf16(float v0, float v1) {
    return pack2(__float2half_rn(v0), __float2half_rn(v1));
}
#define CP_COMMIT() asm volatile("cp.async.commit_group;")
#define CP_WAIT0()  asm volatile("cp.async.wait_group 0;")
#define BAR_N(id, n) asm volatile("bar.sync %0, %1;" :: "r"(id), "n"(n) : "memory")

// ---- prologue: convert all weights f32 -> f16 blob ([chunk64][n][k]) -------
__global__ void convert_weights(Params p) {
    int idx = blockIdx.x * blockDim.x + threadIdx.x;
    if (idx >= BLOB_N) return;
    float v;
    if (idx < 8192) {                       // L0: 256n x 32k
        int n = idx >> 5, kk = idx & 31;
        v = (kk < 30) ? __ldg(&p.W[0][kk * 256 + n]) : 0.f;
    } else if (idx < 532480) {              // L1..L8: 4 chunks x 256n x 64k
        int i = idx - 8192;
        int L = 1 + i / 65536;
        int r = i & 65535;
        int gk = (r >> 14) * 64 + (r & 63);
        int n  = (r >> 6) & 255;
        v = (L <= 7) ? __ldg(&p.W[L][(size_t)gk * 256 + n])
                     : __ldg(&p.W[8][(size_t)gk * 257 + n + 1]);
    } else {                                // Wc0
        int i = idx - 532480;
        if (i < 32768) {                    // 4 chunks x 128n x 64k
            int gk = (i >> 13) * 64 + (i & 63);
            int n  = (i >> 6) & 127;
            v = __ldg(&p.Wc0[(size_t)gk * 128 + n]);
        } else {                            // tail: 128n x 16k
            int j = i - 32768;
            int n = j >> 4, gk = 256 + (j & 15);
            v = (gk < 268) ? __ldg(&p.Wc0[(size_t)gk * 128 + n]) : 0.f;
        }
    }
    g_whi[idx] = __float2half_rn(v);
}

// ---- stage a W-slice of one chunk (16B cp.async; 64-thread wn-group) -------
// kw halves per blob row; smem row stride 144 B always.
__device__ __forceinline__ void stage_grp(uint32_t dstb, const __half* hs,
                                          int n0, int NG, int kw, int csh,
                                          int tl) {
    int cpr = 1 << csh;                    // 16B copies per row (kw/8)
    int total = NG * cpr;
#pragma unroll 1
    for (int idx = tl; idx < total; idx += 64) {
        int n = n0 + (idx >> csh);
        int j = idx & (cpr - 1);
        const __half* s = hs + n * kw + j * 8;
        uint32_t dd = dstb + n * 144 + j * 16;
        asm volatile("cp.async.cg.shared.global [%0], [%1], 16;"
                     :: "r"(dd), "l"(s));
    }
}
__device__ __forceinline__ int csh_of(int kw) {
    return (kw == 64) ? 3 : (kw == 32) ? 2 : 1;
}

// ---- GEMM: acc = A[64 x K] @ W[K x NW]; 64-K chunks, decoupled wn-groups ---
// Prefetch (next_base>=0) ONLY legal when next layer has the same NW
// (otherwise rows cross wn-group ownership and race: the R11 color bug).
template<int NTILES>
__device__ __forceinline__ void gemm_layer(char* g, uint32_t sb, int base,
                                           int K, int t, int lane, int wm,
                                           int wn, float acc[][4], int& buf,
                                           bool pre, int next_base) {
    constexpr int NW = NTILES * 32;
    constexpr int NG = NW / 4;
#pragma unroll
    for (int i = 0; i < 2 * NTILES; i++)
#pragma unroll
        for (int j = 0; j < 4; j++) acc[i][j] = 0.f;

    const int tl = t & 63;
    const int bar_id = 1 + (t >> 6);       // 1 + wn
    const int n0 = wn * NG;
    const int nch = (K + 63) >> 6;

    // ldmatrix lane bases
    const uint32_t a_base = sb + A_HI + (uint32_t)(wm * 32 + (lane & 15)) * SA_B
                          + (uint32_t)(lane >> 4) * 16;
    const int q = lane >> 3;
    const uint32_t b_lane = (uint32_t)(((lane & 7) + ((q >> 1) << 3)) * 144
                                       + (q & 1) * 16);

    if (!pre) {                            // chunk 0 not prefetched
        int kw = min(64, K);
        stage_grp(sb + W_BASE + (buf & 1) * W_BUFB, g_whi + base,
                  n0, NG, kw, csh_of(kw), tl);
        CP_COMMIT();
    }

    auto do_ks = [&](uint32_t wb, int kg, int kl) {
        uint32_t ah[2][4];
        ldsm4(ah[0], a_base + (uint32_t)kg * 2);
        ldsm4(ah[1], a_base + 16 * SA_B + (uint32_t)kg * 2);
#pragma unroll
        for (int ntp = 0; ntp < NTILES / 2; ntp++) {
            uint32_t bb = wb + (uint32_t)((wn * (NTILES * 8) + ntp * 16) * 144)
                        + b_lane + (uint32_t)kl * 2;
            uint32_t bh[4];
            ldsm4(bh, bb);
#pragma unroll
            for (int mt = 0; mt < 2; mt++)
#pragma unroll
                for (int sub = 0; sub < 2; sub++)
                    mma16816(acc[mt * NTILES + 2 * ntp + sub],
                             ah[mt][0], ah[mt][1], ah[mt][2], ah[mt][3],
                             bh[2 * sub], bh[2 * sub + 1]);
        }
    };

#pragma unroll 1
    for (int c = 0; c < nch; c++) {
        CP_WAIT0();                        // chunk c arrived (this thread)
        BAR_N(bar_id, 64);                 // publish; orders c-1 reads too
        if (c + 1 < nch) {
            int kw2 = min(64, K - (c + 1) * 64);
            int off = base + NW * 64 * (c + 1);
            stage_grp(sb + W_BASE + ((buf + c + 1) & 1) * W_BUFB,
                      g_whi + off, n0, NG, kw2, csh_of(kw2), tl);
            CP_COMMIT();
        } else if (next_base >= 0) {       // prefetch next layer chunk 0
            stage_grp(sb + W_BASE + ((buf + nch) & 1) * W_BUFB,
                      g_whi + next_base, n0, NG, 64, 3, tl);
            CP_COMMIT();
        }
        uint32_t wb = sb + W_BASE + (uint32_t)(((buf + c) & 1) * W_BUFB);
        int ksteps = min(64, K - c * 64) >> 4;
        if (ksteps == 4) {                 // common path: straight-line
            do_ks(wb, c * 64,      0);
            do_ks(wb, c * 64 + 16, 16);
            do_ks(wb, c * 64 + 32, 32);
            do_ks(wb, c * 64 + 48, 48);
        } else {
#pragma unroll 1
            for (int s = 0; s < ksteps; s++)
                do_ks(wb, c * 64 + s * 16, s * 16);
        }
    }
    buf += nch;
}

// ---- epilogue: bias(+ReLU) from global, f16 back into A --------------------
// Row-group barriers: A rows [wm*32,+32) touched only by warps sharing wm
// (warps wm, wm+2, wm+4, wm+6 -> 128 threads at named bar 5+wm).
template<int NTILES, bool FULL>
__device__ __forceinline__ void epilogue_A(char* g, int lane, int wm, int wn,
                                           float acc[][4],
                                           const float* __restrict__ bias_g) {
    if (FULL) __syncthreads();
    else      BAR_N(5 + wm, 128);          // row-group gemm A-reads done
    const int g8 = lane >> 2, tig = lane & 3;
#pragma unroll
    for (int mt = 0; mt < 2; mt++) {
#pragma unroll
        for (int nt = 0; nt < NTILES; nt++) {
            int r1 = wm * 32 + mt * 16 + g8, r2 = r1 + 8;
            int cb = wn * (NTILES * 8) + nt * 8 + tig * 2;
            float* a = acc[mt * NTILES + nt];
            float b0 = __ldg(&bias_g[cb]), b1 = __ldg(&bias_g[cb + 1]);
            *(uint32_t*)(g + A_HI + r1 * SA_B + cb * 2) =
                packf16(fmaxf(a[0] + b0, 0.f), fmaxf(a[1] + b1, 0.f));
            *(uint32_t*)(g + A_HI + r2 * SA_B + cb * 2) =
                packf16(fmaxf(a[2] + b0, 0.f), fmaxf(a[3] + b1, 0.f));
        }
    }
    BAR_N(5 + wm, 128);                    // writes visible to row-group
}

// color epilogue: bias + ReLU -> hc f32 (overlays W region; full syncs)
__device__ __forceinline__ void epilogue_HC(char* g, int lane, int wm, int wn,
                                            float acc[][4],
                                            const float* __restrict__ bias_g) {
    __syncthreads();                       // all groups' A/W reads done
    const int g8 = lane >> 2, tig = lane & 3;
#pragma unroll
    for (int mt = 0; mt < 2; mt++) {
#pragma unroll
        for (int nt = 0; nt < 4; nt++) {
            int r1 = wm * 32 + mt * 16 + g8, r2 = r1 + 8;
            int cb = wn * 32 + nt * 8 + tig * 2;
            float* a = acc[mt * 4 + nt];
            float b0 = __ldg(&bias_g[cb]), b1 = __ldg(&bias_g[cb + 1]);
            float2 v1 = make_float2(fmaxf(a[0] + b0, 0.f), fmaxf(a[1] + b1, 0.f));
            float2 v2 = make_float2(fmaxf(a[2] + b0, 0.f), fmaxf(a[3] + b1, 0.f));
            *(float2*)(g + HCOFF + r1 * SHC_B + cb * 4) = v1;
            *(float2*)(g + HCOFF + r2 * SHC_B + cb * 4) = v2;
        }
    }
    __syncthreads();
}

// ---- main kernel -----------------------------------------------------------
__global__ void __launch_bounds__(NT, 2)
nerf_hmma_kernel(Params p, float* __restrict__ out, int ns) {
    extern __shared__ char g[];
    uint32_t sb = (uint32_t)__cvta_generic_to_shared(g);
    int t = threadIdx.x, lane = t & 31, w = t >> 5;
    int wm = w & 1, wn = w >> 1;
    int s0 = blockIdx.x * 64;
    float acc[16][4];
    int buf = 0;

    // stage x -> A cols 0..31 (k>=30 zero); 4 threads/row, 8 k each
    {
        int r = t >> 2, q = t & 3;
        const float* xr = p.x + (size_t)(s0 + r) * 30;
#pragma unroll
        for (int pr = 0; pr < 4; pr++) {
            int k = q * 8 + pr * 2;
            float v0 = (k     < 30) ? xr[k]     : 0.f;
            float v1 = (k + 1 < 30) ? xr[k + 1] : 0.f;
            *(uint32_t*)(g + A_HI + r * SA_B + k * 2) = packf16(v0, v1);
        }
    }
    __syncthreads();

    // layer 0: 30 -> 256 (1 chunk kw=32; prefetches L1 chunk 0)
    gemm_layer<8>(g, sb, 0, 32, t, lane, wm, wn, acc, buf, false, 8192);
    epilogue_A<8, false>(g, lane, wm, wn, acc, p.b[0]);

    // layers 1..7: 256 -> 256 (4 chunks each)
#pragma unroll 1
    for (int L = 1; L <= 7; L++) {
        int nb = (L < 7) ? 8192 + L * 65536 : 466944;
        gemm_layer<8>(g, sb, 8192 + (L - 1) * 65536, 256, t, lane, wm, wn,
                      acc, buf, true, nb);
        epilogue_A<8, false>(g, lane, wm, wn, acc, p.b[L]);
    }

    // layer 8: 256 -> 257 (GEMM cols 1..256; col 0 = sigma scalar path)
    // NO prefetch here: next layer has NW=128 (row ownership changes).
    ((float*)(g + WCOL0))[t] = __ldg(&p.W[8][(size_t)t * 257]);
    gemm_layer<8>(g, sb, 466944, 256, t, lane, wm, wn, acc, buf, true, -1);
    {   // sigma from A (layer-8 input, f16) before epilogue overwrites A
        __syncthreads();                   // all gemm done; WCOL0 visible
        int r = t >> 2, q = t & 3;
        const float* wc = (const float*)(g + WCOL0);
        float s = 0.f;
#pragma unroll 4
        for (int k = q * 64; k < q * 64 + 64; k++) {
            float hv = __half2float(*(const __half*)(g + A_HI + r * SA_B + k * 2));
            s += hv * wc[k];
        }
        s += __shfl_xor_sync(0xffffffffu, s, 1);
        s += __shfl_xor_sync(0xffffffffu, s, 2);
        if (!q && (s0 + r) < ns) out[s0 + r] = fmaxf(s + __ldg(&p.b[8][0]), 0.f);
    }
    epilogue_A<8, true>(g, lane, wm, wn, acc, p.b[8] + 1);  // fx -> A 0..255

    // stage d -> A cols 256..267, zero 268..271
    {
        int r = t >> 2, q = t & 3;
        const float* dr = p.d + (size_t)(s0 + r) * 12;
#pragma unroll
        for (int pr = 0; pr < 2; pr++) {
            int kg = 256 + q * 4 + pr * 2;
            float v0 = (kg     < 268) ? dr[kg - 256]     : 0.f;
            float v1 = (kg + 1 < 268) ? dr[kg + 1 - 256] : 0.f;
            *(uint32_t*)(g + A_HI + r * SA_B + kg * 2) = packf16(v0, v1);
        }
    }
    for (int i = t; i < 384; i += NT) ((float*)(g + WC1O))[i] = __ldg(&p.Wc1[i]);
    __syncthreads();                       // all writes visible; all L8 W
                                           // reads done before color staging

    // color layer 0: 268 -> 128 (K=272: 4x64 + 16 tail; stages own chunks)
    gemm_layer<4>(g, sb, 532480, 272, t, lane, wm, wn, acc, buf, false, -1);
    epilogue_HC(g, lane, wm, wn, acc, p.bc0);

    // head: c = relu(hc @ Wc1 + bc1)
    if (t < 192) {
        int r = t / 3, j = t - r * 3;
        const float* hc  = (const float*)(g + HCOFF + r * SHC_B);
        const float* wc1 = (const float*)(g + WC1O);
        float s = 0.f;
#pragma unroll 4
        for (int k = 0; k < 128; k++) s += hc[k] * wc1[k * 3 + j];
        if ((s0 + r) < ns)
            out[(size_t)ns + (size_t)(s0 + r) * 3 + j] = fmaxf(s + __ldg(&p.bc1[j]), 0.f);
    }
}

extern "C" void kernel_launch(void* const* d_in, const int* in_sizes, int n_in,
                              void* d_out, int out_size) {
    Params p;
    p.x = (const float*)d_in[0];
    p.d = (const float*)d_in[1];
    for (int i = 0; i < 9; i++) {
        p.W[i] = (const float*)d_in[2 + 2 * i];
        p.b[i] = (const float*)d_in[3 + 2 * i];
    }
    p.Wc0 = (const float*)d_in[20];
    p.bc0 = (const float*)d_in[21];
    p.Wc1 = (const float*)d_in[22];
    p.bc1 = (const float*)d_in[23];

    int ns = in_sizes[0] / 30;   // 262144
    convert_weights<<<(BLOB_N + 511) / 512, 512>>>(p);
    cudaFuncSetAttribute(nerf_hmma_kernel,
                         cudaFuncAttributeMaxDynamicSharedMemorySize, SMEM_SZ);
    int grid = (ns + 63) / 64;   // 4096
    nerf_hmma_kernel<<<grid, NT, SMEM_SZ>>>(p, (float*)d_out, ns);
}